// round 1
// baseline (speedup 1.0000x reference)
#include <cuda_runtime.h>

#define N 8192
#define G 296              // kernel-1 grid (2 CTAs per SM on 148 SMs)
#define TPB 256
#define F4_PER_ROW (N / 4)               // 2048 float4 per row
#define F4_PER_THR (F4_PER_ROW / TPB)    // 8 float4 per thread per row

// Scratch (allocation-free rule: __device__ globals)
__device__ float g_partial[(size_t)G * N];   // per-CTA column partial sums (~9.7 MB)
__device__ float g_norm[N];                  // norm per row

// ---------------------------------------------------------------------------
// Kernel 1: single pass over ts (256 MB).
// Each CTA round-robins over rows. For each row:
//   - load the full row into registers (coalesced float4), square in place
//   - block-reduce sum of squares + extract diag element
//   - norm = min(diag/(rowsum-diag), 1);  w = norm * V[row]
//   - acc[j] += w * T[row][j]  (pure register accumulation; each thread owns
//     the same 32 columns every row)
// Finally dump the column partials to g_partial.
// ---------------------------------------------------------------------------
__global__ __launch_bounds__(TPB) void nuiv_k1(const float* __restrict__ ts,
                                               const float* __restrict__ state) {
    __shared__ float s_sum[TPB / 32];
    __shared__ float s_dia[TPB / 32];
    __shared__ float s_bsum, s_bdia;

    const int tid  = threadIdx.x;
    const int lane = tid & 31;
    const int wid  = tid >> 5;

    float4 acc[F4_PER_THR];
#pragma unroll
    for (int k = 0; k < F4_PER_THR; k++) acc[k] = make_float4(0.f, 0.f, 0.f, 0.f);

    for (int row = blockIdx.x; row < N; row += G) {
        const float4* rp = reinterpret_cast<const float4*>(ts + (size_t)row * N);

        float4 v[F4_PER_THR];
        float  sum   = 0.f;
        float  diag2 = 0.f;
#pragma unroll
        for (int k = 0; k < F4_PER_THR; k++) {
            float4 x = rp[tid + k * TPB];
            x.x *= x.x; x.y *= x.y; x.z *= x.z; x.w *= x.w;  // T = ts^2
            v[k] = x;
            sum += (x.x + x.y) + (x.z + x.w);
            const int base = 4 * (tid + k * TPB);
            if (row >= base && row < base + 4) {
                const int r = row - base;
                diag2 = (r == 0) ? x.x : (r == 1) ? x.y : (r == 2) ? x.z : x.w;
            }
        }

        // warp reduce (sum; diag2 is nonzero in exactly one lane so sum works)
#pragma unroll
        for (int off = 16; off > 0; off >>= 1) {
            sum   += __shfl_xor_sync(0xFFFFFFFFu, sum,   off);
            diag2 += __shfl_xor_sync(0xFFFFFFFFu, diag2, off);
        }
        if (lane == 0) { s_sum[wid] = sum; s_dia[wid] = diag2; }
        __syncthreads();
        if (wid == 0) {
            float bs = (lane < TPB / 32) ? s_sum[lane] : 0.f;
            float bd = (lane < TPB / 32) ? s_dia[lane] : 0.f;
#pragma unroll
            for (int off = 4; off > 0; off >>= 1) {
                bs += __shfl_xor_sync(0xFFFFFFFFu, bs, off);
                bd += __shfl_xor_sync(0xFFFFFFFFu, bd, off);
            }
            if (lane == 0) { s_bsum = bs; s_bdia = bd; }
        }
        __syncthreads();

        const float rowsum = s_bsum;
        const float dg     = s_bdia;
        const float nrm    = fminf(dg / (rowsum - dg), 1.0f);
        const float w      = nrm * __ldg(state + 3 * row + 2);   // V[row]
        if (tid == 0) g_norm[row] = nrm;
        __syncthreads();   // protect s_bsum/s_bdia before next row overwrites

#pragma unroll
        for (int k = 0; k < F4_PER_THR; k++) {
            acc[k].x = fmaf(w, v[k].x, acc[k].x);
            acc[k].y = fmaf(w, v[k].y, acc[k].y);
            acc[k].z = fmaf(w, v[k].z, acc[k].z);
            acc[k].w = fmaf(w, v[k].w, acc[k].w);
        }
    }

    float4* pp = reinterpret_cast<float4*>(g_partial + (size_t)blockIdx.x * N);
#pragma unroll
    for (int k = 0; k < F4_PER_THR; k++) pp[tid + k * TPB] = acc[k];
}

// ---------------------------------------------------------------------------
// Kernel 2: reduce per-CTA partials into coupling, do all elementwise math,
// write interleaved output [dU, dI, dV] per index.
// ---------------------------------------------------------------------------
__global__ __launch_bounds__(TPB) void nuiv_k2(const float* __restrict__ ts,
                                               const float* __restrict__ state,
                                               const float* __restrict__ betas,
                                               const float* __restrict__ deltas,
                                               const float* __restrict__ cs,
                                               const float* __restrict__ ps,
                                               float* __restrict__ out) {
    const int j = blockIdx.x * TPB + threadIdx.x;
    if (j >= N) return;

    // column sum over G partials (coalesced across threads); 4-way ILP
    float s0 = 0.f, s1 = 0.f, s2 = 0.f, s3 = 0.f;
    int g = 0;
    for (; g + 4 <= G; g += 4) {
        s0 += g_partial[(size_t)(g + 0) * N + j];
        s1 += g_partial[(size_t)(g + 1) * N + j];
        s2 += g_partial[(size_t)(g + 2) * N + j];
        s3 += g_partial[(size_t)(g + 3) * N + j];
    }
    for (; g < G; g++) s0 += g_partial[(size_t)g * N + j];
    const float colsum = (s0 + s1) + (s2 + s3);

    const float tjj  = __ldg(ts + (size_t)j * N + j);
    const float diag = tjj * tjj;
    const float nrm  = g_norm[j];

    const float U = state[3 * j + 0];
    const float I = state[3 * j + 1];
    const float V = state[3 * j + 2];
    const float b = betas[j],  b2 = b * b;
    const float d = deltas[j], d2 = d * d;
    const float c = cs[j],     c2 = c * c;
    const float p = ps[j],     p2 = p * p;

    const float bUV      = b2 * U * V;
    const float coupling = colsum - nrm * diag * V;   // remove i==j term
    const float dV       = p2 * I - c2 * V - diag + coupling;

    out[3 * j + 0] = -bUV;
    out[3 * j + 1] = bUV - d2 * I;
    out[3 * j + 2] = dV;
}

extern "C" void kernel_launch(void* const* d_in, const int* in_sizes, int n_in,
                              void* d_out, int out_size) {
    // inputs: 0=t, 1=state(3N), 2=betas, 3=deltas, 4=cs, 5=ps, 6=ts(N*N)
    const float* state  = (const float*)d_in[1];
    const float* betas  = (const float*)d_in[2];
    const float* deltas = (const float*)d_in[3];
    const float* cs     = (const float*)d_in[4];
    const float* ps     = (const float*)d_in[5];
    const float* ts     = (const float*)d_in[6];
    float* out = (float*)d_out;

    nuiv_k1<<<G, TPB>>>(ts, state);
    nuiv_k2<<<(N + TPB - 1) / TPB, TPB>>>(ts, state, betas, deltas, cs, ps, out);
}

// round 2
// speedup vs baseline: 3.3793x; 3.3793x over previous
#include <cuda_runtime.h>

#define N 8192
#define G 296              // kernel-1 grid (2 CTAs per SM on 148 SMs)
#define TPB 256
#define F4_PER_ROW (N / 4)               // 2048 float4 per row
#define F4_PER_THR (F4_PER_ROW / TPB)    // 8 float4 per thread per row

// Scratch (allocation-free rule: __device__ globals)
__device__ float g_partial[(size_t)G * N];   // per-CTA column partial sums (~9.7 MB)
__device__ float g_norm[N];                  // norm per row
__device__ float g_diag[N];                  // T diag per row (ts[i][i]^2)

// ---------------------------------------------------------------------------
// Kernel 1: single pass over ts (256 MB), software-pipelined.
// Double-buffered row registers: prefetch row r+G while reducing/accumulating
// row r, so DRAM latency overlaps with the per-row block reduction.
// ---------------------------------------------------------------------------
__global__ __launch_bounds__(TPB, 2) void nuiv_k1(const float* __restrict__ ts,
                                                  const float* __restrict__ state) {
    __shared__ float s_sum[2][TPB / 32];
    __shared__ float s_dia[2][TPB / 32];
    __shared__ float s_bsum[2], s_bdia[2];

    const int tid  = threadIdx.x;
    const int lane = tid & 31;
    const int wid  = tid >> 5;

    const float4* ts4 = reinterpret_cast<const float4*>(ts);

    float4 acc[F4_PER_THR];
#pragma unroll
    for (int k = 0; k < F4_PER_THR; k++) acc[k] = make_float4(0.f, 0.f, 0.f, 0.f);

    int row = blockIdx.x;
    if (row < N) {
        // preload first row
        float4 vc[F4_PER_THR];
        {
            const float4* rp = ts4 + (size_t)row * F4_PER_ROW;
#pragma unroll
            for (int k = 0; k < F4_PER_THR; k++) vc[k] = rp[tid + k * TPB];
        }

        int p = 0;
        for (; row < N; row += G, p ^= 1) {
            // ---- prefetch next row (loads issue before any barrier/wait) ----
            const int nrow = (row + G < N) ? row + G : row;   // clamped, dead on last iter
            const float4* rpn = ts4 + (size_t)nrow * F4_PER_ROW;
            float4 vn[F4_PER_THR];
#pragma unroll
            for (int k = 0; k < F4_PER_THR; k++) vn[k] = rpn[tid + k * TPB];

            // ---- consume current row: square in place, sumsq + diag ----
            float sum = 0.f, diag2 = 0.f;
#pragma unroll
            for (int k = 0; k < F4_PER_THR; k++) {
                float4 x = vc[k];
                x.x *= x.x; x.y *= x.y; x.z *= x.z; x.w *= x.w;   // T = ts^2
                vc[k] = x;
                sum += (x.x + x.y) + (x.z + x.w);
                const int base = 4 * (tid + k * TPB);
                if (row >= base && row < base + 4) {
                    const int r = row - base;
                    diag2 = (r == 0) ? x.x : (r == 1) ? x.y : (r == 2) ? x.z : x.w;
                }
            }

            // ---- block reduce (2 barriers, parity-buffered shared) ----
#pragma unroll
            for (int off = 16; off > 0; off >>= 1) {
                sum   += __shfl_xor_sync(0xFFFFFFFFu, sum,   off);
                diag2 += __shfl_xor_sync(0xFFFFFFFFu, diag2, off);
            }
            if (lane == 0) { s_sum[p][wid] = sum; s_dia[p][wid] = diag2; }
            __syncthreads();
            if (wid == 0) {
                float bs = (lane < TPB / 32) ? s_sum[p][lane] : 0.f;
                float bd = (lane < TPB / 32) ? s_dia[p][lane] : 0.f;
#pragma unroll
                for (int off = 4; off > 0; off >>= 1) {
                    bs += __shfl_xor_sync(0xFFFFFFFFu, bs, off);
                    bd += __shfl_xor_sync(0xFFFFFFFFu, bd, off);
                }
                if (lane == 0) { s_bsum[p] = bs; s_bdia[p] = bd; }
            }
            __syncthreads();

            const float rowsum = s_bsum[p];
            const float dg     = s_bdia[p];
            const float nrm    = fminf(dg / (rowsum - dg), 1.0f);
            const float w      = nrm * __ldg(state + 3 * row + 2);   // V[row]
            if (tid == 0) { g_norm[row] = nrm; g_diag[row] = dg; }

            // ---- accumulate column partials in registers ----
#pragma unroll
            for (int k = 0; k < F4_PER_THR; k++) {
                acc[k].x = fmaf(w, vc[k].x, acc[k].x);
                acc[k].y = fmaf(w, vc[k].y, acc[k].y);
                acc[k].z = fmaf(w, vc[k].z, acc[k].z);
                acc[k].w = fmaf(w, vc[k].w, acc[k].w);
            }

            // rotate buffers
#pragma unroll
            for (int k = 0; k < F4_PER_THR; k++) vc[k] = vn[k];
        }
    }

    float4* pp = reinterpret_cast<float4*>(g_partial + (size_t)blockIdx.x * N);
#pragma unroll
    for (int k = 0; k < F4_PER_THR; k++) pp[tid + k * TPB] = acc[k];
}

// ---------------------------------------------------------------------------
// Kernel 2: 256 blocks, each handles 32 columns. 8 threads per column sum the
// G=296 partials (coalesced: a warp = one g row x 32 consecutive columns),
// shared-memory combine, then the elementwise math + interleaved output.
// ---------------------------------------------------------------------------
#define K2_BLOCKS (N / 32)

__global__ __launch_bounds__(TPB) void nuiv_k2(const float* __restrict__ state,
                                               const float* __restrict__ betas,
                                               const float* __restrict__ deltas,
                                               const float* __restrict__ cs,
                                               const float* __restrict__ ps,
                                               float* __restrict__ out) {
    __shared__ float sh[8][32];

    const int lane = threadIdx.x & 31;   // column within block
    const int grp  = threadIdx.x >> 5;   // g stride group (0..7)
    const int j    = blockIdx.x * 32 + lane;

    float s0 = 0.f, s1 = 0.f, s2 = 0.f, s3 = 0.f;
    int g = grp;
    // G=296 -> 37 iters per group; unroll 4 for MLP
    for (; g + 24 < G; g += 32) {
        s0 += g_partial[(size_t)(g +  0) * N + j];
        s1 += g_partial[(size_t)(g +  8) * N + j];
        s2 += g_partial[(size_t)(g + 16) * N + j];
        s3 += g_partial[(size_t)(g + 24) * N + j];
    }
    for (; g < G; g += 8) s0 += g_partial[(size_t)g * N + j];
    sh[grp][lane] = (s0 + s1) + (s2 + s3);
    __syncthreads();

    if (threadIdx.x < 32) {
        float colsum = 0.f;
#pragma unroll
        for (int k = 0; k < 8; k++) colsum += sh[k][lane];

        const float diag = g_diag[j];
        const float nrm  = g_norm[j];

        const float U = state[3 * j + 0];
        const float I = state[3 * j + 1];
        const float V = state[3 * j + 2];
        const float b = betas[j],  b2 = b * b;
        const float d = deltas[j], d2 = d * d;
        const float c = cs[j],     c2 = c * c;
        const float p = ps[j],     p2 = p * p;

        const float bUV      = b2 * U * V;
        const float coupling = colsum - nrm * diag * V;   // remove i==j term
        const float dV       = p2 * I - c2 * V - diag + coupling;

        out[3 * j + 0] = -bUV;
        out[3 * j + 1] = bUV - d2 * I;
        out[3 * j + 2] = dV;
    }
}

extern "C" void kernel_launch(void* const* d_in, const int* in_sizes, int n_in,
                              void* d_out, int out_size) {
    // inputs: 0=t, 1=state(3N), 2=betas, 3=deltas, 4=cs, 5=ps, 6=ts(N*N)
    const float* state  = (const float*)d_in[1];
    const float* betas  = (const float*)d_in[2];
    const float* deltas = (const float*)d_in[3];
    const float* cs     = (const float*)d_in[4];
    const float* ps     = (const float*)d_in[5];
    const float* ts     = (const float*)d_in[6];
    float* out = (float*)d_out;

    nuiv_k1<<<G, TPB>>>(ts, state);
    nuiv_k2<<<K2_BLOCKS, TPB>>>(state, betas, deltas, cs, ps, out);
}

// round 3
// speedup vs baseline: 3.3834x; 1.0012x over previous
#include <cuda_runtime.h>

#define N 8192
#define G 296              // kernel-1 grid (2 CTAs per SM on 148 SMs)
#define TPB 256
#define F4_PER_ROW (N / 4)               // 2048 float4 per row
#define F4_PER_THR (F4_PER_ROW / TPB)    // 8 float4 per thread per row

// Scratch (allocation-free rule: __device__ globals)
__device__ float g_partial[(size_t)G * N];   // per-CTA column partial sums (~9.7 MB)
__device__ float g_norm[N];                  // norm per row
__device__ float g_diag[N];                  // T diag per row (ts[i][i]^2)

// ---------------------------------------------------------------------------
// Kernel 1: single pass over ts (256 MB), software-pipelined.
// Double-buffered row registers: prefetch row r+G while reducing/accumulating
// row r, so DRAM latency overlaps with the per-row block reduction.
// ---------------------------------------------------------------------------
__global__ __launch_bounds__(TPB, 2) void nuiv_k1(const float* __restrict__ ts,
                                                  const float* __restrict__ state) {
    __shared__ float s_sum[2][TPB / 32];
    __shared__ float s_dia[2][TPB / 32];
    __shared__ float s_bsum[2], s_bdia[2];

    const int tid  = threadIdx.x;
    const int lane = tid & 31;
    const int wid  = tid >> 5;

    const float4* ts4 = reinterpret_cast<const float4*>(ts);

    float4 acc[F4_PER_THR];
#pragma unroll
    for (int k = 0; k < F4_PER_THR; k++) acc[k] = make_float4(0.f, 0.f, 0.f, 0.f);

    int row = blockIdx.x;
    if (row < N) {
        // preload first row
        float4 vc[F4_PER_THR];
        {
            const float4* rp = ts4 + (size_t)row * F4_PER_ROW;
#pragma unroll
            for (int k = 0; k < F4_PER_THR; k++) vc[k] = rp[tid + k * TPB];
        }

        int p = 0;
        for (; row < N; row += G, p ^= 1) {
            // ---- prefetch next row (loads issue before any barrier/wait) ----
            const int nrow = (row + G < N) ? row + G : row;   // clamped, dead on last iter
            const float4* rpn = ts4 + (size_t)nrow * F4_PER_ROW;
            float4 vn[F4_PER_THR];
#pragma unroll
            for (int k = 0; k < F4_PER_THR; k++) vn[k] = rpn[tid + k * TPB];

            // ---- consume current row: square in place, sumsq + diag ----
            float sum = 0.f, diag2 = 0.f;
#pragma unroll
            for (int k = 0; k < F4_PER_THR; k++) {
                float4 x = vc[k];
                x.x *= x.x; x.y *= x.y; x.z *= x.z; x.w *= x.w;   // T = ts^2
                vc[k] = x;
                sum += (x.x + x.y) + (x.z + x.w);
                const int base = 4 * (tid + k * TPB);
                if (row >= base && row < base + 4) {
                    const int r = row - base;
                    diag2 = (r == 0) ? x.x : (r == 1) ? x.y : (r == 2) ? x.z : x.w;
                }
            }

            // ---- block reduce (2 barriers, parity-buffered shared) ----
#pragma unroll
            for (int off = 16; off > 0; off >>= 1) {
                sum   += __shfl_xor_sync(0xFFFFFFFFu, sum,   off);
                diag2 += __shfl_xor_sync(0xFFFFFFFFu, diag2, off);
            }
            if (lane == 0) { s_sum[p][wid] = sum; s_dia[p][wid] = diag2; }
            __syncthreads();
            if (wid == 0) {
                float bs = (lane < TPB / 32) ? s_sum[p][lane] : 0.f;
                float bd = (lane < TPB / 32) ? s_dia[p][lane] : 0.f;
#pragma unroll
                for (int off = 4; off > 0; off >>= 1) {
                    bs += __shfl_xor_sync(0xFFFFFFFFu, bs, off);
                    bd += __shfl_xor_sync(0xFFFFFFFFu, bd, off);
                }
                if (lane == 0) { s_bsum[p] = bs; s_bdia[p] = bd; }
            }
            __syncthreads();

            const float rowsum = s_bsum[p];
            const float dg     = s_bdia[p];
            const float nrm    = fminf(dg / (rowsum - dg), 1.0f);
            const float w      = nrm * __ldg(state + 3 * row + 2);   // V[row]
            if (tid == 0) { g_norm[row] = nrm; g_diag[row] = dg; }

            // ---- accumulate column partials in registers ----
#pragma unroll
            for (int k = 0; k < F4_PER_THR; k++) {
                acc[k].x = fmaf(w, vc[k].x, acc[k].x);
                acc[k].y = fmaf(w, vc[k].y, acc[k].y);
                acc[k].z = fmaf(w, vc[k].z, acc[k].z);
                acc[k].w = fmaf(w, vc[k].w, acc[k].w);
            }

            // rotate buffers
#pragma unroll
            for (int k = 0; k < F4_PER_THR; k++) vc[k] = vn[k];
        }
    }

    float4* pp = reinterpret_cast<float4*>(g_partial + (size_t)blockIdx.x * N);
#pragma unroll
    for (int k = 0; k < F4_PER_THR; k++) pp[tid + k * TPB] = acc[k];
}

// ---------------------------------------------------------------------------
// Kernel 2: 256 blocks, each handles 32 columns. 8 threads per column sum the
// G=296 partials (coalesced: a warp = one g row x 32 consecutive columns),
// shared-memory combine, then the elementwise math + interleaved output.
// ---------------------------------------------------------------------------
#define K2_BLOCKS (N / 32)

__global__ __launch_bounds__(TPB) void nuiv_k2(const float* __restrict__ state,
                                               const float* __restrict__ betas,
                                               const float* __restrict__ deltas,
                                               const float* __restrict__ cs,
                                               const float* __restrict__ ps,
                                               float* __restrict__ out) {
    __shared__ float sh[8][32];

    const int lane = threadIdx.x & 31;   // column within block
    const int grp  = threadIdx.x >> 5;   // g stride group (0..7)
    const int j    = blockIdx.x * 32 + lane;

    float s0 = 0.f, s1 = 0.f, s2 = 0.f, s3 = 0.f;
    int g = grp;
    // G=296 -> 37 iters per group; unroll 4 for MLP
    for (; g + 24 < G; g += 32) {
        s0 += g_partial[(size_t)(g +  0) * N + j];
        s1 += g_partial[(size_t)(g +  8) * N + j];
        s2 += g_partial[(size_t)(g + 16) * N + j];
        s3 += g_partial[(size_t)(g + 24) * N + j];
    }
    for (; g < G; g += 8) s0 += g_partial[(size_t)g * N + j];
    sh[grp][lane] = (s0 + s1) + (s2 + s3);
    __syncthreads();

    if (threadIdx.x < 32) {
        float colsum = 0.f;
#pragma unroll
        for (int k = 0; k < 8; k++) colsum += sh[k][lane];

        const float diag = g_diag[j];
        const float nrm  = g_norm[j];

        const float U = state[3 * j + 0];
        const float I = state[3 * j + 1];
        const float V = state[3 * j + 2];
        const float b = betas[j],  b2 = b * b;
        const float d = deltas[j], d2 = d * d;
        const float c = cs[j],     c2 = c * c;
        const float p = ps[j],     p2 = p * p;

        const float bUV      = b2 * U * V;
        const float coupling = colsum - nrm * diag * V;   // remove i==j term
        const float dV       = p2 * I - c2 * V - diag + coupling;

        out[3 * j + 0] = -bUV;
        out[3 * j + 1] = bUV - d2 * I;
        out[3 * j + 2] = dV;
    }
}

extern "C" void kernel_launch(void* const* d_in, const int* in_sizes, int n_in,
                              void* d_out, int out_size) {
    // inputs: 0=t, 1=state(3N), 2=betas, 3=deltas, 4=cs, 5=ps, 6=ts(N*N)
    const float* state  = (const float*)d_in[1];
    const float* betas  = (const float*)d_in[2];
    const float* deltas = (const float*)d_in[3];
    const float* cs     = (const float*)d_in[4];
    const float* ps     = (const float*)d_in[5];
    const float* ts     = (const float*)d_in[6];
    float* out = (float*)d_out;

    nuiv_k1<<<G, TPB>>>(ts, state);
    nuiv_k2<<<K2_BLOCKS, TPB>>>(state, betas, deltas, cs, ps, out);
}

// round 4
// speedup vs baseline: 3.5290x; 1.0430x over previous
#include <cuda_runtime.h>

#define N 8192
#define G 296              // kernel-1 grid (2 CTAs per SM on 148 SMs)
#define TPB 256
#define F4_PER_ROW (N / 4)               // 2048 float4 per row
#define F4_PER_THR (F4_PER_ROW / TPB)    // 8 float4 per thread per row

// Scratch (allocation-free rule: __device__ globals)
__device__ float g_partial[(size_t)G * N];   // per-CTA column partial sums (~9.7 MB)
__device__ float g_norm[N];                  // norm per row
__device__ float g_diag[N];                  // T diag per row (ts[i][i]^2)

// ---------------------------------------------------------------------------
// Kernel 1: single pass over ts (256 MB), software-pipelined.
// Double-buffered row registers: prefetch row r+G while reducing/accumulating
// row r. ONE barrier per row: warp shfl reduce -> shared -> barrier -> every
// thread sums the 8 warp partials via broadcast LDS (parity double-buffered).
// ---------------------------------------------------------------------------
__global__ __launch_bounds__(TPB, 2) void nuiv_k1(const float* __restrict__ ts,
                                                  const float* __restrict__ state) {
    __shared__ float s_sum[2][TPB / 32];
    __shared__ float s_dia[2][TPB / 32];

    const int tid  = threadIdx.x;
    const int lane = tid & 31;
    const int wid  = tid >> 5;

    const float4* ts4 = reinterpret_cast<const float4*>(ts);

    float4 acc[F4_PER_THR];
#pragma unroll
    for (int k = 0; k < F4_PER_THR; k++) acc[k] = make_float4(0.f, 0.f, 0.f, 0.f);

    int row = blockIdx.x;
    if (row < N) {
        // preload first row
        float4 vc[F4_PER_THR];
        {
            const float4* rp = ts4 + (size_t)row * F4_PER_ROW;
#pragma unroll
            for (int k = 0; k < F4_PER_THR; k++) vc[k] = rp[tid + k * TPB];
        }

        int p = 0;
        for (; row < N; row += G, p ^= 1) {
            // ---- prefetch next row (loads issue before any barrier/wait) ----
            float4 vn[F4_PER_THR];
            if (row + G < N) {
                const float4* rpn = ts4 + (size_t)(row + G) * F4_PER_ROW;
#pragma unroll
                for (int k = 0; k < F4_PER_THR; k++) vn[k] = rpn[tid + k * TPB];
            }

            // ---- consume current row: square in place, sumsq + diag ----
            float sum = 0.f, diag2 = 0.f;
#pragma unroll
            for (int k = 0; k < F4_PER_THR; k++) {
                float4 x = vc[k];
                x.x *= x.x; x.y *= x.y; x.z *= x.z; x.w *= x.w;   // T = ts^2
                vc[k] = x;
                sum += (x.x + x.y) + (x.z + x.w);
                const int base = 4 * (tid + k * TPB);
                if (row >= base && row < base + 4) {
                    const int r = row - base;
                    diag2 = (r == 0) ? x.x : (r == 1) ? x.y : (r == 2) ? x.z : x.w;
                }
            }

            // ---- warp reduce, then ONE barrier + broadcast combine ----
#pragma unroll
            for (int off = 16; off > 0; off >>= 1) {
                sum   += __shfl_xor_sync(0xFFFFFFFFu, sum,   off);
                diag2 += __shfl_xor_sync(0xFFFFFFFFu, diag2, off);
            }
            if (lane == 0) { s_sum[p][wid] = sum; s_dia[p][wid] = diag2; }
            __syncthreads();

            float rowsum = 0.f, dg = 0.f;
#pragma unroll
            for (int w = 0; w < TPB / 32; w++) {
                rowsum += s_sum[p][w];
                dg     += s_dia[p][w];
            }

            const float nrm = fminf(dg / (rowsum - dg), 1.0f);
            const float w   = nrm * __ldg(state + 3 * row + 2);   // V[row]
            if (tid == 0) { g_norm[row] = nrm; g_diag[row] = dg; }

            // ---- accumulate column partials in registers ----
#pragma unroll
            for (int k = 0; k < F4_PER_THR; k++) {
                acc[k].x = fmaf(w, vc[k].x, acc[k].x);
                acc[k].y = fmaf(w, vc[k].y, acc[k].y);
                acc[k].z = fmaf(w, vc[k].z, acc[k].z);
                acc[k].w = fmaf(w, vc[k].w, acc[k].w);
            }

            // rotate buffers
#pragma unroll
            for (int k = 0; k < F4_PER_THR; k++) vc[k] = vn[k];
        }
    }

    float4* pp = reinterpret_cast<float4*>(g_partial + (size_t)blockIdx.x * N);
#pragma unroll
    for (int k = 0; k < F4_PER_THR; k++) pp[tid + k * TPB] = acc[k];
}

// ---------------------------------------------------------------------------
// Kernel 2: 1024 blocks x 256 threads; each block owns 8 columns, 32 threads
// per column. Each thread fully unrolls its 9-10 independent partial loads
// (MLP ~10), then 2 shfl levels + tiny shared combine reduce the g-dimension.
// ---------------------------------------------------------------------------
#define K2_GRID (N / 8)   // 1024

__global__ __launch_bounds__(TPB) void nuiv_k2(const float* __restrict__ state,
                                               const float* __restrict__ betas,
                                               const float* __restrict__ deltas,
                                               const float* __restrict__ cs,
                                               const float* __restrict__ ps,
                                               float* __restrict__ out) {
    __shared__ float sh[TPB / 32][8];

    const int t     = threadIdx.x;
    const int col   = t & 7;          // column within block (0..7)
    const int gslot = t >> 3;         // 0..31
    const int wrp   = t >> 5;
    const int j     = blockIdx.x * 8 + col;

    // G = 296 = 32*9 + 8: every gslot does 9 loads, gslot<8 does one extra.
    float a[9];
#pragma unroll
    for (int i = 0; i < 9; i++)
        a[i] = g_partial[(size_t)(gslot + 32 * i) * N + j];
    float extra = (gslot < 8) ? g_partial[(size_t)(gslot + 288) * N + j] : 0.f;

    float s = ((a[0] + a[1]) + (a[2] + a[3])) +
              ((a[4] + a[5]) + (a[6] + a[7])) + (a[8] + extra);

    // reduce across gslot within warp (gslot bits 0,1 of warp-local slot)
    s += __shfl_xor_sync(0xFFFFFFFFu, s, 8);
    s += __shfl_xor_sync(0xFFFFFFFFu, s, 16);
    if ((t & 31) < 8) sh[wrp][col] = s;
    __syncthreads();

    if (t < 8) {
        float colsum = 0.f;
#pragma unroll
        for (int w = 0; w < TPB / 32; w++) colsum += sh[w][t];

        const int jj = blockIdx.x * 8 + t;
        const float diag = g_diag[jj];
        const float nrm  = g_norm[jj];

        const float U = state[3 * jj + 0];
        const float I = state[3 * jj + 1];
        const float V = state[3 * jj + 2];
        const float b = betas[jj],  b2 = b * b;
        const float d = deltas[jj], d2 = d * d;
        const float c = cs[jj],     c2 = c * c;
        const float p = ps[jj],     p2 = p * p;

        const float bUV      = b2 * U * V;
        const float coupling = colsum - nrm * diag * V;   // remove i==j term
        const float dV       = p2 * I - c2 * V - diag + coupling;

        out[3 * jj + 0] = -bUV;
        out[3 * jj + 1] = bUV - d2 * I;
        out[3 * jj + 2] = dV;
    }
}

extern "C" void kernel_launch(void* const* d_in, const int* in_sizes, int n_in,
                              void* d_out, int out_size) {
    // inputs: 0=t, 1=state(3N), 2=betas, 3=deltas, 4=cs, 5=ps, 6=ts(N*N)
    const float* state  = (const float*)d_in[1];
    const float* betas  = (const float*)d_in[2];
    const float* deltas = (const float*)d_in[3];
    const float* cs     = (const float*)d_in[4];
    const float* ps     = (const float*)d_in[5];
    const float* ts     = (const float*)d_in[6];
    float* out = (float*)d_out;

    nuiv_k1<<<G, TPB>>>(ts, state);
    nuiv_k2<<<K2_GRID, TPB>>>(state, betas, deltas, cs, ps, out);
}